// round 3
// baseline (speedup 1.0000x reference)
#include <cuda_runtime.h>

// ---------------------------------------------------------------------------
// QuantumNet: 2-qubit circuit -> closed-form quadratic form.
//
// Per sample:  out = p^T R p,
//   p = (c0*c1, c0*s1, s0*c1, -s0*s1),  ci = cos(x_i/2), si = sin(x_i/2)
//   R = Re( D^H (U^H P U) D ),  P = diag(1,1,0,0),  D = diag(1,-i,-i,1)
//   U = prod_l  CNOT01 * RX1(w_l1) * RX0(w_l0)   (later layers multiply on left)
// R depends only on q_weights -> computed once by a 1-thread prep kernel.
// ---------------------------------------------------------------------------

__device__ float d_R[16];   // symmetric 4x4 real quadratic-form matrix

__device__ __forceinline__ float2 cmul(float2 a, float2 b) {
    return make_float2(fmaf(a.x, b.x, -a.y * b.y), fmaf(a.x, b.y, a.y * b.x));
}
__device__ __forceinline__ float2 cadd(float2 a, float2 b) {
    return make_float2(a.x + b.x, a.y + b.y);
}

__global__ void prep_kernel(const float* __restrict__ w, int n_layers) {
    if (threadIdx.x != 0 || blockIdx.x != 0) return;

    // U = I (4x4 complex), basis index = 2*q0 + q1
    float2 U[4][4];
    for (int r = 0; r < 4; r++)
        for (int k = 0; k < 4; k++)
            U[r][k] = make_float2(r == k ? 1.0f : 0.0f, 0.0f);

    for (int l = 0; l < n_layers; l++) {
        float w0 = w[2 * l + 0];
        float w1 = w[2 * l + 1];

        // RX on qubit 0: mixes row pairs (0,2) and (1,3)
        {
            float c = cosf(0.5f * w0), s = sinf(0.5f * w0);
            float2 fc = make_float2(c, 0.0f);
            float2 fs = make_float2(0.0f, -s);   // -i*sin
            for (int k = 0; k < 4; k++) {
                for (int base = 0; base < 2; base++) {
                    float2 t0 = U[base][k], t2 = U[base + 2][k];
                    U[base][k]     = cadd(cmul(fc, t0), cmul(fs, t2));
                    U[base + 2][k] = cadd(cmul(fs, t0), cmul(fc, t2));
                }
            }
        }
        // RX on qubit 1: mixes row pairs (0,1) and (2,3)
        {
            float c = cosf(0.5f * w1), s = sinf(0.5f * w1);
            float2 fc = make_float2(c, 0.0f);
            float2 fs = make_float2(0.0f, -s);
            for (int k = 0; k < 4; k++) {
                for (int base = 0; base < 4; base += 2) {
                    float2 t0 = U[base][k], t1 = U[base + 1][k];
                    U[base][k]     = cadd(cmul(fc, t0), cmul(fs, t1));
                    U[base + 1][k] = cadd(cmul(fs, t0), cmul(fc, t1));
                }
            }
        }
        // CNOT (control q0, target q1): swap rows 2 and 3 (|10> <-> |11>)
        for (int k = 0; k < 4; k++) {
            float2 t = U[2][k]; U[2][k] = U[3][k]; U[3][k] = t;
        }
    }

    // M_jk = sum_{r in {0,1}} conj(U[r][j]) * U[r][k]   (P = diag(1,1,0,0))
    // R_jk = Re( conj(d_j) * M_jk * d_k ),  d = (1, -i, -i, 1)
    float2 d[4] = { make_float2(1, 0), make_float2(0, -1),
                    make_float2(0, -1), make_float2(1, 0) };
    for (int j = 0; j < 4; j++) {
        for (int k = 0; k < 4; k++) {
            float2 m = make_float2(0.0f, 0.0f);
            for (int r = 0; r < 2; r++) {
                float2 cj = make_float2(U[r][j].x, -U[r][j].y);
                m = cadd(m, cmul(cj, U[r][k]));
            }
            float2 cdj = make_float2(d[j].x, -d[j].y);
            float2 nn = cmul(cmul(cdj, m), d[k]);
            d_R[j * 4 + k] = nn.x;
        }
    }
}

__device__ __forceinline__ float eval_sample(float x0, float x1, const float* R) {
    float s0, c0, s1, c1;
    __sincosf(0.5f * x0, &s0, &c0);
    __sincosf(0.5f * x1, &s1, &c1);
    float p0 = c0 * c1;
    float p1 = c0 * s1;
    float p2 = s0 * c1;
    float p3 = -s0 * s1;
    float t0 = fmaf(R[0],  p0, fmaf(R[1],  p1, fmaf(R[2],  p2, R[3]  * p3)));
    float t1 = fmaf(R[4],  p0, fmaf(R[5],  p1, fmaf(R[6],  p2, R[7]  * p3)));
    float t2 = fmaf(R[8],  p0, fmaf(R[9],  p1, fmaf(R[10], p2, R[11] * p3)));
    float t3 = fmaf(R[12], p0, fmaf(R[13], p1, fmaf(R[14], p2, R[15] * p3)));
    return fmaf(p0, t0, fmaf(p1, t1, fmaf(p2, t2, p3 * t3)));
}

__global__ void __launch_bounds__(256)
qnet_kernel(const float* __restrict__ x, float* __restrict__ out, int n) {
    __shared__ float sR[16];
    if (threadIdx.x < 16) sR[threadIdx.x] = d_R[threadIdx.x];
    __syncthreads();

    float R[16];
#pragma unroll
    for (int i = 0; i < 16; i++) R[i] = sR[i];

    long long quad = (long long)blockIdx.x * blockDim.x + threadIdx.x;
    long long i0 = quad * 4;

    if (i0 + 3 < (long long)n) {
        // 4 samples: two coalesced float4 loads, one float4 store
        const float4* x4 = (const float4*)x;
        float4 a = x4[quad * 2 + 0];   // x0_0, x1_0, x0_1, x1_1
        float4 b = x4[quad * 2 + 1];   // x0_2, x1_2, x0_3, x1_3
        float4 o;
        o.x = eval_sample(a.x, a.y, R);
        o.y = eval_sample(a.z, a.w, R);
        o.z = eval_sample(b.x, b.y, R);
        o.w = eval_sample(b.z, b.w, R);
        ((float4*)out)[quad] = o;
    } else {
        for (long long i = i0; i < (long long)n; i++)
            out[i] = eval_sample(x[2 * i + 0], x[2 * i + 1], R);
    }
}

extern "C" void kernel_launch(void* const* d_in, const int* in_sizes, int n_in,
                              void* d_out, int out_size) {
    const float* x = (const float*)d_in[0];        // [B, 2] float32
    const float* w = (const float*)d_in[1];        // [N_LAYERS, 2] float32
    float* out = (float*)d_out;                    // [B, 1] float32

    int n = in_sizes[0] / 2;          // number of samples B
    int n_layers = in_sizes[1] / 2;

    prep_kernel<<<1, 1>>>(w, n_layers);

    int quads = (n + 3) / 4;
    int blocks = (quads + 255) / 256;
    qnet_kernel<<<blocks, 256>>>(x, out, n);
}